// round 2
// baseline (speedup 1.0000x reference)
#include <cuda_runtime.h>
#include <math.h>

// Problem constants
#define Bb   2
#define Ss   2048
#define Dd   1024
#define NHh  16
#define HDd  64
#define MM   (Bb*Ss)          // 4096 rows for projection GEMMs
#define PLANE (Ss*Ss)         // 4194304 (per (b,h) score plane)
#define BSD  (Bb*Ss*Dd)       // 4194304 elements

// ---------------- scratch (device globals; no allocations allowed) ----------
__device__ float g_Q[BSD];
__device__ float g_K[BSD];
__device__ float g_V[BSD];
__device__ float g_Qh[BSD];    // [b,h,s,d]
__device__ float g_Kh[BSD];
__device__ float g_Vh[BSD];
__device__ float g_AH[BSD];    // attn output per head [b,h,s,d]
__device__ float g_A[BSD];     // merged back to [b,s,D]
__device__ float g_Sc[134217728];  // scores/probs scratch [b,h,l,n] (536 MB)

// ---------------------------------------------------------------------------
// Generic fp32 GEMM + bias: C[M,1024] = A[M,1024] @ W[1024,1024] + bias
// Tiles 128x128, BK=8, 256 threads, 8x8 micro-tile.
// ---------------------------------------------------------------------------
__global__ __launch_bounds__(256) void sgemm_bias_kernel(
    const float* __restrict__ A, const float* __restrict__ W,
    const float* __restrict__ bias, float* __restrict__ C)
{
    __shared__ float As[8][128];
    __shared__ float Bs[8][128];
    const int bm = blockIdx.y * 128;
    const int bn = blockIdx.x * 128;
    const int tid = threadIdx.x;
    const int tx = tid & 15;
    const int ty = tid >> 4;
    const int arow = tid >> 1;
    const int ak   = (tid & 1) * 4;
    const int brow = tid >> 5;
    const int bcol = (tid & 31) * 4;

    float acc[8][8];
#pragma unroll
    for (int i = 0; i < 8; ++i)
#pragma unroll
        for (int j = 0; j < 8; ++j) acc[i][j] = 0.f;

    const float* Aptr = A + (size_t)(bm + arow) * Dd + ak;
    const float* Wptr = W + (size_t)brow * Dd + bn + bcol;

    for (int k0 = 0; k0 < Dd; k0 += 8) {
        float4 av = *(const float4*)(Aptr + k0);
        float4 wv = *(const float4*)(Wptr + (size_t)k0 * Dd);
        As[ak+0][arow] = av.x;
        As[ak+1][arow] = av.y;
        As[ak+2][arow] = av.z;
        As[ak+3][arow] = av.w;
        *(float4*)&Bs[brow][bcol] = wv;
        __syncthreads();
#pragma unroll
        for (int k = 0; k < 8; ++k) {
            float a[8], b[8];
            *(float4*)(a)   = *(const float4*)&As[k][ty*8];
            *(float4*)(a+4) = *(const float4*)&As[k][ty*8+4];
            *(float4*)(b)   = *(const float4*)&Bs[k][tx*8];
            *(float4*)(b+4) = *(const float4*)&Bs[k][tx*8+4];
#pragma unroll
            for (int i = 0; i < 8; ++i)
#pragma unroll
                for (int j = 0; j < 8; ++j)
                    acc[i][j] = fmaf(a[i], b[j], acc[i][j]);
        }
        __syncthreads();
    }
    float bb[8];
#pragma unroll
    for (int j = 0; j < 8; ++j) bb[j] = bias[bn + tx*8 + j];
#pragma unroll
    for (int i = 0; i < 8; ++i) {
        float* cp = C + (size_t)(bm + ty*8 + i) * Dd + bn + tx*8;
        float4 o0 = {acc[i][0]+bb[0], acc[i][1]+bb[1], acc[i][2]+bb[2], acc[i][3]+bb[3]};
        float4 o1 = {acc[i][4]+bb[4], acc[i][5]+bb[5], acc[i][6]+bb[6], acc[i][7]+bb[7]};
        *(float4*)(cp)     = o0;
        *(float4*)(cp + 4) = o1;
    }
}

// ---------------------------------------------------------------------------
// Head split: out[b][h][s][d] = in[b][s][d*16+h]
// ---------------------------------------------------------------------------
__global__ __launch_bounds__(256) void head_split_kernel(
    const float* __restrict__ in, float* __restrict__ out)
{
    int i = blockIdx.x * 256 + threadIdx.x;     // output-linear index
    int d  = i & 63;
    int s  = (i >> 6) & 2047;
    int hb = i >> 17;                            // b*16+h
    int h  = hb & 15;
    int b  = hb >> 4;
    out[i] = in[(size_t)(b*2048 + s) * 1024 + d*16 + h];
}

// ---------------------------------------------------------------------------
// Scores: per plane z=(b*16+h): Sc[l,n] = 0.125 * dot(Qh[l,:], Kh[n,:]), K=64
// NT GEMM 2048x2048x64, tiles 128x128, BK=16, 8x8 micro.
// ---------------------------------------------------------------------------
__global__ __launch_bounds__(256) void scores_kernel()
{
    __shared__ float As[16][128];
    __shared__ float Bs[16][128];
    const int z  = blockIdx.z;
    const int bm = blockIdx.y * 128;
    const int bn = blockIdx.x * 128;
    const int tid = threadIdx.x;
    const int tx = tid & 15;
    const int ty = tid >> 4;
    const float* Q  = g_Qh + (size_t)z * (Ss*HDd);
    const float* Kh = g_Kh + (size_t)z * (Ss*HDd);

    float acc[8][8];
#pragma unroll
    for (int i = 0; i < 8; ++i)
#pragma unroll
        for (int j = 0; j < 8; ++j) acc[i][j] = 0.f;

    for (int k0 = 0; k0 < HDd; k0 += 16) {
#pragma unroll
        for (int it = 0; it < 2; ++it) {
            int i  = tid + it*256;
            int row = i >> 2;
            int k4  = (i & 3) * 4;
            float4 qa = *(const float4*)(Q  + (size_t)(bm+row)*HDd + k0 + k4);
            float4 kb = *(const float4*)(Kh + (size_t)(bn+row)*HDd + k0 + k4);
            As[k4+0][row]=qa.x; As[k4+1][row]=qa.y; As[k4+2][row]=qa.z; As[k4+3][row]=qa.w;
            Bs[k4+0][row]=kb.x; Bs[k4+1][row]=kb.y; Bs[k4+2][row]=kb.z; Bs[k4+3][row]=kb.w;
        }
        __syncthreads();
#pragma unroll
        for (int k = 0; k < 16; ++k) {
            float a[8], b[8];
            *(float4*)(a)   = *(const float4*)&As[k][ty*8];
            *(float4*)(a+4) = *(const float4*)&As[k][ty*8+4];
            *(float4*)(b)   = *(const float4*)&Bs[k][tx*8];
            *(float4*)(b+4) = *(const float4*)&Bs[k][tx*8+4];
#pragma unroll
            for (int i = 0; i < 8; ++i)
#pragma unroll
                for (int j = 0; j < 8; ++j)
                    acc[i][j] = fmaf(a[i], b[j], acc[i][j]);
        }
        __syncthreads();
    }
    float* out = g_Sc + (size_t)z * PLANE;
#pragma unroll
    for (int i = 0; i < 8; ++i) {
        float* cp = out + (size_t)(bm + ty*8 + i) * Ss + bn + tx*8;
        float4 o0 = {0.125f*acc[i][0], 0.125f*acc[i][1], 0.125f*acc[i][2], 0.125f*acc[i][3]};
        float4 o1 = {0.125f*acc[i][4], 0.125f*acc[i][5], 0.125f*acc[i][6], 0.125f*acc[i][7]};
        *(float4*)(cp)     = o0;
        *(float4*)(cp + 4) = o1;
    }
}

// ---------------------------------------------------------------------------
// Softmax over the HEAD axis. One thread per (b,l,n).
// Reads raw scores from g_Sc (plane-strided, coalesced), writes probs in
// [b,l,n,h] layout to d_out AND normalized values back in-place to g_Sc.
// ---------------------------------------------------------------------------
__global__ __launch_bounds__(256) void softmax_kernel(float* __restrict__ probs)
{
    int i = blockIdx.x * 256 + threadIdx.x;     // (b*2048 + l)*2048 + n
    int n = i & 2047;
    int l = (i >> 11) & 2047;
    int b = i >> 22;
    size_t off = (size_t)l * Ss + n;

    float s[16];
#pragma unroll
    for (int h = 0; h < 16; ++h)
        s[h] = g_Sc[(size_t)(b*16 + h) * PLANE + off];

    float m = s[0];
#pragma unroll
    for (int h = 1; h < 16; ++h) m = fmaxf(m, s[h]);
    float sum = 0.f;
#pragma unroll
    for (int h = 0; h < 16; ++h) { s[h] = __expf(s[h] - m); sum += s[h]; }
    float r = 1.0f / sum;

    float* po = probs + (size_t)i * 16;
#pragma unroll
    for (int h4 = 0; h4 < 16; h4 += 4) {
        float4 o = {s[h4]*r, s[h4+1]*r, s[h4+2]*r, s[h4+3]*r};
        *(float4*)(po + h4) = o;
    }
#pragma unroll
    for (int h = 0; h < 16; ++h)
        g_Sc[(size_t)(b*16 + h) * PLANE + off] = s[h] * r;
}

// ---------------------------------------------------------------------------
// Attn*V: per plane z=(b,h): O[l,d] = sum_n P[l,n] * V[n,d]
// M=2048, N=64, K=2048. Tiles 128x64, BK=16, 8x4 micro.
// ---------------------------------------------------------------------------
__global__ __launch_bounds__(256) void attnv_kernel()
{
    __shared__ float Ps[16][128];
    __shared__ float Vs[16][64];
    const int z  = blockIdx.y;
    const int bm = blockIdx.x * 128;
    const int tid = threadIdx.x;
    const int tx = tid & 15;
    const int ty = tid >> 4;
    const float* P = g_Sc + (size_t)z * PLANE;
    const float* V = g_Vh + (size_t)z * (Ss*HDd);
    float* O = g_AH + (size_t)z * (Ss*HDd);
    const int vr = tid >> 4;
    const int vc = (tid & 15) * 4;

    float acc[8][4];
#pragma unroll
    for (int i = 0; i < 8; ++i)
#pragma unroll
        for (int j = 0; j < 4; ++j) acc[i][j] = 0.f;

    for (int k0 = 0; k0 < Ss; k0 += 16) {
#pragma unroll
        for (int it = 0; it < 2; ++it) {
            int i  = tid + it*256;
            int row = i >> 2;
            int k4  = (i & 3) * 4;
            float4 pv = *(const float4*)(P + (size_t)(bm+row)*Ss + k0 + k4);
            Ps[k4+0][row]=pv.x; Ps[k4+1][row]=pv.y; Ps[k4+2][row]=pv.z; Ps[k4+3][row]=pv.w;
        }
        *(float4*)&Vs[vr][vc] = *(const float4*)(V + (size_t)(k0+vr)*HDd + vc);
        __syncthreads();
#pragma unroll
        for (int k = 0; k < 16; ++k) {
            float a[8], b[4];
            *(float4*)(a)   = *(const float4*)&Ps[k][ty*8];
            *(float4*)(a+4) = *(const float4*)&Ps[k][ty*8+4];
            *(float4*)(b)   = *(const float4*)&Vs[k][tx*4];
#pragma unroll
            for (int i = 0; i < 8; ++i)
#pragma unroll
                for (int j = 0; j < 4; ++j)
                    acc[i][j] = fmaf(a[i], b[j], acc[i][j]);
        }
        __syncthreads();
    }
#pragma unroll
    for (int i = 0; i < 8; ++i) {
        float4 o = {acc[i][0], acc[i][1], acc[i][2], acc[i][3]};
        *(float4*)(O + (size_t)(bm + ty*8 + i)*HDd + tx*4) = o;
    }
}

// ---------------------------------------------------------------------------
// Head merge: g_A[b][s][d*16+h] = g_AH[b][h][s][d]
// ---------------------------------------------------------------------------
__global__ __launch_bounds__(256) void head_merge_kernel()
{
    int i = blockIdx.x * 256 + threadIdx.x;     // g_A linear index
    int j = i & 1023;
    int s = (i >> 10) & 2047;
    int b = i >> 21;
    int h = j & 15;
    int d = j >> 4;
    g_A[i] = g_AH[(size_t)((b*16 + h)*2048 + s) * 64 + d];
}

// ---------------------------------------------------------------------------
extern "C" void kernel_launch(void* const* d_in, const int* in_sizes, int n_in,
                              void* d_out, int out_size)
{
    const float* query = (const float*)d_in[0];
    const float* key   = (const float*)d_in[1];
    const float* value = (const float*)d_in[2];
    const float* Wq = (const float*)d_in[3];  const float* bq = (const float*)d_in[4];
    const float* Wk = (const float*)d_in[5];  const float* bk = (const float*)d_in[6];
    const float* Wv = (const float*)d_in[7];  const float* bv = (const float*)d_in[8];
    const float* Wo = (const float*)d_in[9];  const float* bo = (const float*)d_in[10];

    float* out   = (float*)d_out;
    float* probs = out + BSD;

    void* p;
    cudaGetSymbolAddress(&p, g_Q);  float* gQ  = (float*)p;
    cudaGetSymbolAddress(&p, g_K);  float* gK  = (float*)p;
    cudaGetSymbolAddress(&p, g_V);  float* gV  = (float*)p;
    cudaGetSymbolAddress(&p, g_Qh); float* gQh = (float*)p;
    cudaGetSymbolAddress(&p, g_Kh); float* gKh = (float*)p;
    cudaGetSymbolAddress(&p, g_Vh); float* gVh = (float*)p;
    cudaGetSymbolAddress(&p, g_A);  float* gA  = (float*)p;

    dim3 gemm_grid(Dd/128, MM/128);   // (8, 32)

    // 1) Projections
    sgemm_bias_kernel<<<gemm_grid, 256>>>(query, Wq, bq, gQ);
    sgemm_bias_kernel<<<gemm_grid, 256>>>(key,   Wk, bk, gK);
    sgemm_bias_kernel<<<gemm_grid, 256>>>(value, Wv, bv, gV);

    // 2) Head split into [b,h,s,d]
    head_split_kernel<<<BSD/256, 256>>>(gQ, gQh);
    head_split_kernel<<<BSD/256, 256>>>(gK, gKh);
    head_split_kernel<<<BSD/256, 256>>>(gV, gVh);

    // 3) Per-head scores (raw, scaled) into g_Sc
    scores_kernel<<<dim3(Ss/128, Ss/128, Bb*NHh), 256>>>();

    // 4) Softmax over heads: writes probs output + normalized in-place scratch
    softmax_kernel<<<(Bb*Ss*Ss)/256, 256>>>(probs);

    // 5) Attn * V per head
    attnv_kernel<<<dim3(Ss/128, Bb*NHh), 256>>>();

    // 6) Merge heads back to [b,s,D]
    head_merge_kernel<<<BSD/256, 256>>>();

    // 7) Output projection straight into d_out
    sgemm_bias_kernel<<<gemm_grid, 256>>>(gA, Wo, bo, out);
}

// round 3
// speedup vs baseline: 1.9312x; 1.9312x over previous
#include <cuda_runtime.h>
#include <math.h>
#include <stdint.h>

// Problem constants
#define Bb   2
#define Ss   2048
#define Dd   1024
#define NHh  16
#define HDd  64
#define MM   (Bb*Ss)
#define PLANE (Ss*Ss)
#define BSD  (Bb*Ss*Dd)

// ---------------- scratch (device globals) ----------------
__device__ float g_Q[BSD];
__device__ float g_K[BSD];
__device__ float g_V[BSD];
__device__ float g_Qh[BSD];    // [b,h,s,d]
__device__ float g_Kh[BSD];
__device__ float g_Vh[BSD];
__device__ float g_AH[BSD];    // attn out per head [b,h,s,d]
__device__ float g_A[BSD];     // merged [b,s,D]
__device__ float g_Sc[134217728];  // scores/probs scratch [b,h,l,n]

// ---------------------------------------------------------------------------
// tf32 helpers
// ---------------------------------------------------------------------------
__device__ __forceinline__ uint32_t f2tf(float f) {
    uint32_t u;
    asm("cvt.rna.tf32.f32 %0, %1;" : "=r"(u) : "f"(f));
    return u;
}

// D += A(16x8) * B(8x8), tf32 inputs, f32 accum
__device__ __forceinline__ void mma_tf32(float* c, const uint32_t* a, const uint32_t* b) {
    asm volatile(
        "mma.sync.aligned.m16n8k8.row.col.f32.tf32.tf32.f32 "
        "{%0,%1,%2,%3}, {%4,%5,%6,%7}, {%8,%9}, {%0,%1,%2,%3};\n"
        : "+f"(c[0]), "+f"(c[1]), "+f"(c[2]), "+f"(c[3])
        : "r"(a[0]), "r"(a[1]), "r"(a[2]), "r"(a[3]), "r"(b[0]), "r"(b[1]));
}

// ---------------------------------------------------------------------------
// Projection GEMM (tf32): C[M,1024] = A[M,1024] @ W[1024,1024] + bias
// Block tile 128x128, BK=32, 256 threads, 8 warps (2m x 4n), warp tile 64x32.
// ---------------------------------------------------------------------------
__global__ __launch_bounds__(256) void gemm_tf32_bias(
    const float* __restrict__ A, const float* __restrict__ W,
    const float* __restrict__ bias, float* __restrict__ C)
{
    __shared__ uint32_t As[128][36];   // [m][k], pad->36: frag banks (4g+tg) distinct
    __shared__ uint32_t Bs[32][136];   // [k][n], pad->136: frag banks (8tg+n) distinct
    const int tid  = threadIdx.x;
    const int lane = tid & 31, w = tid >> 5;
    const int g = lane >> 2, tg = lane & 3;
    const int bm = blockIdx.y * 128, bn = blockIdx.x * 128;
    const int warpM = (w >> 2) * 64, warpN = (w & 3) * 32;

    float acc[4][4][4];
#pragma unroll
    for (int mt = 0; mt < 4; ++mt)
#pragma unroll
        for (int nt = 0; nt < 4; ++nt)
#pragma unroll
            for (int i = 0; i < 4; ++i) acc[mt][nt][i] = 0.f;

    for (int k0 = 0; k0 < Dd; k0 += 32) {
        // Load A tile 128x32 (1024 float4, 4/thread)
#pragma unroll
        for (int it = 0; it < 4; ++it) {
            int ch = tid + it * 256;
            int m = ch >> 3, kq = (ch & 7) << 2;
            float4 v = *(const float4*)(A + (size_t)(bm + m) * Dd + k0 + kq);
            uint4 u = {f2tf(v.x), f2tf(v.y), f2tf(v.z), f2tf(v.w)};
            *(uint4*)&As[m][kq] = u;
        }
        // Load W tile 32x128 (1024 float4, 4/thread), direct [k][n]
#pragma unroll
        for (int it = 0; it < 4; ++it) {
            int ch = tid + it * 256;
            int kk = ch >> 5, n4 = (ch & 31) << 2;
            float4 v = *(const float4*)(W + (size_t)(k0 + kk) * Dd + bn + n4);
            uint4 u = {f2tf(v.x), f2tf(v.y), f2tf(v.z), f2tf(v.w)};
            *(uint4*)&Bs[kk][n4] = u;
        }
        __syncthreads();
#pragma unroll
        for (int ks = 0; ks < 32; ks += 8) {
            uint32_t af[4][4], bf[4][2];
#pragma unroll
            for (int mt = 0; mt < 4; ++mt) {
                int r = warpM + mt * 16 + g;
                af[mt][0] = As[r][ks + tg];
                af[mt][1] = As[r + 8][ks + tg];
                af[mt][2] = As[r][ks + tg + 4];
                af[mt][3] = As[r + 8][ks + tg + 4];
            }
#pragma unroll
            for (int nt = 0; nt < 4; ++nt) {
                int c = warpN + nt * 8 + g;
                bf[nt][0] = Bs[ks + tg][c];
                bf[nt][1] = Bs[ks + tg + 4][c];
            }
#pragma unroll
            for (int mt = 0; mt < 4; ++mt)
#pragma unroll
                for (int nt = 0; nt < 4; ++nt)
                    mma_tf32(acc[mt][nt], af[mt], bf[nt]);
        }
        __syncthreads();
    }
#pragma unroll
    for (int mt = 0; mt < 4; ++mt)
#pragma unroll
        for (int nt = 0; nt < 4; ++nt) {
            int r0 = bm + warpM + mt * 16 + g;
            int c0 = bn + warpN + nt * 8 + 2 * tg;
            float b0 = bias[c0], b1 = bias[c0 + 1];
            float2 v0 = {acc[mt][nt][0] + b0, acc[mt][nt][1] + b1};
            float2 v1 = {acc[mt][nt][2] + b0, acc[mt][nt][3] + b1};
            *(float2*)(C + (size_t)r0 * Dd + c0) = v0;
            *(float2*)(C + (size_t)(r0 + 8) * Dd + c0) = v1;
        }
}

// ---------------------------------------------------------------------------
// Head split: out[b][h][s][d] = in[b][s][d*16+h]
// ---------------------------------------------------------------------------
__global__ __launch_bounds__(256) void head_split_kernel(
    const float* __restrict__ in, float* __restrict__ out)
{
    int i = blockIdx.x * 256 + threadIdx.x;
    int d  = i & 63;
    int s  = (i >> 6) & 2047;
    int hb = i >> 17;
    int h  = hb & 15;
    int b  = hb >> 4;
    out[i] = in[(size_t)(b*2048 + s) * 1024 + d*16 + h];
}

// ---------------------------------------------------------------------------
// Scores (tf32 NT): per plane z: Sc[l,n] = 0.125 * Qh[l,:] . Kh[n,:], K=64
// Block 128x128, BK=32 (2 iters), 256 threads, 8 warps (2m x 4n), warp 64x32.
// ---------------------------------------------------------------------------
__global__ __launch_bounds__(256) void scores_tf32()
{
    __shared__ uint32_t As[128][36];
    __shared__ uint32_t Bs[32][136];
    const int tid  = threadIdx.x;
    const int lane = tid & 31, w = tid >> 5;
    const int g = lane >> 2, tg = lane & 3;
    const int z  = blockIdx.z;
    const int bm = blockIdx.y * 128, bn = blockIdx.x * 128;
    const int warpM = (w >> 2) * 64, warpN = (w & 3) * 32;
    const float* Q  = g_Qh + (size_t)z * (Ss*HDd);
    const float* Kh = g_Kh + (size_t)z * (Ss*HDd);

    float acc[4][4][4];
#pragma unroll
    for (int mt = 0; mt < 4; ++mt)
#pragma unroll
        for (int nt = 0; nt < 4; ++nt)
#pragma unroll
            for (int i = 0; i < 4; ++i) acc[mt][nt][i] = 0.f;

    for (int k0 = 0; k0 < HDd; k0 += 32) {
        // A: Qh tile 128x32
#pragma unroll
        for (int it = 0; it < 4; ++it) {
            int ch = tid + it * 256;
            int m = ch >> 3, kq = (ch & 7) << 2;
            float4 v = *(const float4*)(Q + (size_t)(bm + m) * HDd + k0 + kq);
            uint4 u = {f2tf(v.x), f2tf(v.y), f2tf(v.z), f2tf(v.w)};
            *(uint4*)&As[m][kq] = u;
        }
        // B: Kh tile 128n x 32k, transpose into Bs[k][n]
#pragma unroll
        for (int it = 0; it < 4; ++it) {
            int ch = tid + it * 256;
            int n = ch >> 3, kq = (ch & 7) << 2;
            float4 v = *(const float4*)(Kh + (size_t)(bn + n) * HDd + k0 + kq);
            Bs[kq + 0][n] = f2tf(v.x);
            Bs[kq + 1][n] = f2tf(v.y);
            Bs[kq + 2][n] = f2tf(v.z);
            Bs[kq + 3][n] = f2tf(v.w);
        }
        __syncthreads();
#pragma unroll
        for (int ks = 0; ks < 32; ks += 8) {
            uint32_t af[4][4], bf[4][2];
#pragma unroll
            for (int mt = 0; mt < 4; ++mt) {
                int r = warpM + mt * 16 + g;
                af[mt][0] = As[r][ks + tg];
                af[mt][1] = As[r + 8][ks + tg];
                af[mt][2] = As[r][ks + tg + 4];
                af[mt][3] = As[r + 8][ks + tg + 4];
            }
#pragma unroll
            for (int nt = 0; nt < 4; ++nt) {
                int c = warpN + nt * 8 + g;
                bf[nt][0] = Bs[ks + tg][c];
                bf[nt][1] = Bs[ks + tg + 4][c];
            }
#pragma unroll
            for (int mt = 0; mt < 4; ++mt)
#pragma unroll
                for (int nt = 0; nt < 4; ++nt)
                    mma_tf32(acc[mt][nt], af[mt], bf[nt]);
        }
        __syncthreads();
    }
    float* out = g_Sc + (size_t)z * PLANE;
#pragma unroll
    for (int mt = 0; mt < 4; ++mt)
#pragma unroll
        for (int nt = 0; nt < 4; ++nt) {
            int r0 = bm + warpM + mt * 16 + g;
            int c0 = bn + warpN + nt * 8 + 2 * tg;
            float2 v0 = {0.125f*acc[mt][nt][0], 0.125f*acc[mt][nt][1]};
            float2 v1 = {0.125f*acc[mt][nt][2], 0.125f*acc[mt][nt][3]};
            *(float2*)(out + (size_t)r0 * Ss + c0) = v0;
            *(float2*)(out + (size_t)(r0 + 8) * Ss + c0) = v1;
        }
}

// ---------------------------------------------------------------------------
// Softmax over HEAD axis, one thread per (b,l,n). Writes probs to d_out and
// normalized values back to g_Sc.
// ---------------------------------------------------------------------------
__global__ __launch_bounds__(256) void softmax_kernel(float* __restrict__ probs)
{
    int i = blockIdx.x * 256 + threadIdx.x;
    int n = i & 2047;
    int l = (i >> 11) & 2047;
    int b = i >> 22;
    size_t off = (size_t)l * Ss + n;

    float s[16];
#pragma unroll
    for (int h = 0; h < 16; ++h)
        s[h] = g_Sc[(size_t)(b*16 + h) * PLANE + off];

    float m = s[0];
#pragma unroll
    for (int h = 1; h < 16; ++h) m = fmaxf(m, s[h]);
    float sum = 0.f;
#pragma unroll
    for (int h = 0; h < 16; ++h) { s[h] = __expf(s[h] - m); sum += s[h]; }
    float r = 1.0f / sum;

    float* po = probs + (size_t)i * 16;
#pragma unroll
    for (int h4 = 0; h4 < 16; h4 += 4) {
        float4 o = {s[h4]*r, s[h4+1]*r, s[h4+2]*r, s[h4+3]*r};
        *(float4*)(po + h4) = o;
    }
#pragma unroll
    for (int h = 0; h < 16; ++h)
        g_Sc[(size_t)(b*16 + h) * PLANE + off] = s[h] * r;
}

// ---------------------------------------------------------------------------
// Attn*V (tf32): per plane z: O[l,d] = sum_n P[l,n] * V[n,d]
// M=2048, N=64, K=2048. Block 128x64, BK=32, 256 threads,
// 8 warps (4m x 2n), warp tile 32x32.
// ---------------------------------------------------------------------------
__global__ __launch_bounds__(256) void attnv_tf32()
{
    __shared__ uint32_t As[128][36];   // P tile [m][k]
    __shared__ uint32_t Bs[32][72];    // V tile [k][n], pad->72 (72%32==8)
    const int tid  = threadIdx.x;
    const int lane = tid & 31, w = tid >> 5;
    const int g = lane >> 2, tg = lane & 3;
    const int z  = blockIdx.y;
    const int bm = blockIdx.x * 128;
    const int warpM = (w >> 1) * 32, warpN = (w & 1) * 32;
    const float* P = g_Sc + (size_t)z * PLANE;
    const float* V = g_Vh + (size_t)z * (Ss*HDd);
    float* O = g_AH + (size_t)z * (Ss*HDd);

    float acc[2][4][4];
#pragma unroll
    for (int mt = 0; mt < 2; ++mt)
#pragma unroll
        for (int nt = 0; nt < 4; ++nt)
#pragma unroll
            for (int i = 0; i < 4; ++i) acc[mt][nt][i] = 0.f;

    for (int k0 = 0; k0 < Ss; k0 += 32) {
        // P tile 128x32 (1024 f4, 4/thread)
#pragma unroll
        for (int it = 0; it < 4; ++it) {
            int ch = tid + it * 256;
            int m = ch >> 3, kq = (ch & 7) << 2;
            float4 v = *(const float4*)(P + (size_t)(bm + m) * Ss + k0 + kq);
            uint4 u = {f2tf(v.x), f2tf(v.y), f2tf(v.z), f2tf(v.w)};
            *(uint4*)&As[m][kq] = u;
        }
        // V tile 32x64 (512 f4, 2/thread), direct [k][n]
#pragma unroll
        for (int it = 0; it < 2; ++it) {
            int ch = tid + it * 256;
            int kk = ch >> 4, n4 = (ch & 15) << 2;
            float4 v = *(const float4*)(V + (size_t)(k0 + kk) * HDd + n4);
            uint4 u = {f2tf(v.x), f2tf(v.y), f2tf(v.z), f2tf(v.w)};
            *(uint4*)&Bs[kk][n4] = u;
        }
        __syncthreads();
#pragma unroll
        for (int ks = 0; ks < 32; ks += 8) {
            uint32_t af[2][4], bf[4][2];
#pragma unroll
            for (int mt = 0; mt < 2; ++mt) {
                int r = warpM + mt * 16 + g;
                af[mt][0] = As[r][ks + tg];
                af[mt][1] = As[r + 8][ks + tg];
                af[mt][2] = As[r][ks + tg + 4];
                af[mt][3] = As[r + 8][ks + tg + 4];
            }
#pragma unroll
            for (int nt = 0; nt < 4; ++nt) {
                int c = warpN + nt * 8 + g;
                bf[nt][0] = Bs[ks + tg][c];
                bf[nt][1] = Bs[ks + tg + 4][c];
            }
#pragma unroll
            for (int mt = 0; mt < 2; ++mt)
#pragma unroll
                for (int nt = 0; nt < 4; ++nt)
                    mma_tf32(acc[mt][nt], af[mt], bf[nt]);
        }
        __syncthreads();
    }
#pragma unroll
    for (int mt = 0; mt < 2; ++mt)
#pragma unroll
        for (int nt = 0; nt < 4; ++nt) {
            int r0 = bm + warpM + mt * 16 + g;
            int c0 = warpN + nt * 8 + 2 * tg;
            float2 v0 = {acc[mt][nt][0], acc[mt][nt][1]};
            float2 v1 = {acc[mt][nt][2], acc[mt][nt][3]};
            *(float2*)(O + (size_t)r0 * HDd + c0) = v0;
            *(float2*)(O + (size_t)(r0 + 8) * HDd + c0) = v1;
        }
}

// ---------------------------------------------------------------------------
// Head merge: g_A[b][s][d*16+h] = g_AH[b][h][s][d]
// ---------------------------------------------------------------------------
__global__ __launch_bounds__(256) void head_merge_kernel()
{
    int i = blockIdx.x * 256 + threadIdx.x;
    int j = i & 1023;
    int s = (i >> 10) & 2047;
    int b = i >> 21;
    int h = j & 15;
    int d = j >> 4;
    g_A[i] = g_AH[(size_t)((b*16 + h)*2048 + s) * 64 + d];
}

// ---------------------------------------------------------------------------
extern "C" void kernel_launch(void* const* d_in, const int* in_sizes, int n_in,
                              void* d_out, int out_size)
{
    const float* query = (const float*)d_in[0];
    const float* key   = (const float*)d_in[1];
    const float* value = (const float*)d_in[2];
    const float* Wq = (const float*)d_in[3];  const float* bq = (const float*)d_in[4];
    const float* Wk = (const float*)d_in[5];  const float* bk = (const float*)d_in[6];
    const float* Wv = (const float*)d_in[7];  const float* bv = (const float*)d_in[8];
    const float* Wo = (const float*)d_in[9];  const float* bo = (const float*)d_in[10];

    float* out   = (float*)d_out;
    float* probs = out + BSD;

    void* p;
    cudaGetSymbolAddress(&p, g_Q);  float* gQ  = (float*)p;
    cudaGetSymbolAddress(&p, g_K);  float* gK  = (float*)p;
    cudaGetSymbolAddress(&p, g_V);  float* gV  = (float*)p;
    cudaGetSymbolAddress(&p, g_Qh); float* gQh = (float*)p;
    cudaGetSymbolAddress(&p, g_Kh); float* gKh = (float*)p;
    cudaGetSymbolAddress(&p, g_Vh); float* gVh = (float*)p;
    cudaGetSymbolAddress(&p, g_A);  float* gA  = (float*)p;

    dim3 gemm_grid(Dd/128, MM/128);   // (8, 32)

    // 1) Projections (tf32 tensor cores)
    gemm_tf32_bias<<<gemm_grid, 256>>>(query, Wq, bq, gQ);
    gemm_tf32_bias<<<gemm_grid, 256>>>(key,   Wk, bk, gK);
    gemm_tf32_bias<<<gemm_grid, 256>>>(value, Wv, bv, gV);

    // 2) Head split into [b,h,s,d]
    head_split_kernel<<<BSD/256, 256>>>(gQ, gQh);
    head_split_kernel<<<BSD/256, 256>>>(gK, gKh);
    head_split_kernel<<<BSD/256, 256>>>(gV, gVh);

    // 3) Per-head scores into g_Sc (tf32)
    scores_tf32<<<dim3(Ss/128, Ss/128, Bb*NHh), 256>>>();

    // 4) Softmax over heads
    softmax_kernel<<<(Bb*(size_t)Ss*Ss)/256, 256>>>(probs);

    // 5) Attn * V per head (tf32)
    attnv_tf32<<<dim3(Ss/128, Bb*NHh), 256>>>();

    // 6) Merge heads
    head_merge_kernel<<<BSD/256, 256>>>();

    // 7) Output projection (tf32)
    gemm_tf32_bias<<<gemm_grid, 256>>>(gA, Wo, bo, out);
}